// round 8
// baseline (speedup 1.0000x reference)
#include <cuda_runtime.h>

// TiDHy collapses algebraically: r stays zero through the scan, so
//   sl_rhat = sum_t mean_b sum_d (b_sd[d] - X[b,t,d])^2   (all T)
//   sl_rbar = same, t >= 1;  temp_loss = 0, r2_losses = 0, r0/r2 = zeros.
// One fused reduction over X (8 MB) + zero-fill of d_out.
//
// R7: 128 CTAs x 512 thr (<=1 CTA/SM, minimal ramp/drain/tail) and U=8
// LDG.128 forced front-batched via inline asm (compiler cannot reassociate)
// -> guaranteed 4 KB in flight per warp, one DRAM round trip per warp.

#define NB 128
#define NT 512

static constexpr int Bc  = 128;                 // batch
static constexpr int Tc  = 32;                  // timesteps
static constexpr int Dc  = 512;                 // input dim
static constexpr int NE4 = Bc * Tc * Dc / 4;    // 524288 float4
static constexpr int GSZ = NB * NT;             // 65536 threads; GSZ*8 == NE4

__device__ float2 g_partials[NB];
__device__ int    g_counter = 0;

__device__ __forceinline__ float4 ldg128(const float4* p) {
    float4 v;
    asm volatile("ld.global.nc.v4.f32 {%0,%1,%2,%3}, [%4];"
                 : "=f"(v.x), "=f"(v.y), "=f"(v.z), "=f"(v.w) : "l"(p));
    return v;
}

__global__ void __launch_bounds__(NT)
tidhy_fused_kernel(const float4* __restrict__ X4,
                   const float4* __restrict__ bsd4,
                   float* __restrict__ out, int out_size)
{
    const int tid  = threadIdx.x;
    const int bid  = blockIdx.x;
    const int gtid = bid * NT + tid;

    // 8 independent LDG.128, front-batched by construction (asm volatile
    // statements keep program order): MLP = 8, one latency round trip.
    const float4* p = X4 + gtid;
    float4 x0 = ldg128(p + 0 * GSZ);
    float4 x1 = ldg128(p + 1 * GSZ);
    float4 x2 = ldg128(p + 2 * GSZ);
    float4 x3 = ldg128(p + 3 * GSZ);
    float4 x4 = ldg128(p + 4 * GSZ);
    float4 x5 = ldg128(p + 5 * GSZ);
    float4 x6 = ldg128(p + 6 * GSZ);
    float4 x7 = ldg128(p + 7 * GSZ);

    // GSZ is a multiple of 128 (=D/4) and 4096 (=D/4*T): d-index and
    // timestep are invariant across this thread's eight loads.
    const float4 bs = __ldg(&bsd4[gtid & 127]);

    // Zero the output tuple (out[0..1] overwritten by the last block below).
    if (gtid < out_size) out[gtid] = 0.0f;

    const bool is_t0 = (((gtid >> 7) & (Tc - 1)) == 0);

    float s = 0.0f;
    {
        float dx, dy, dz, dw;
#define ACC(v) dx = v.x - bs.x; dy = v.y - bs.y; dz = v.z - bs.z; dw = v.w - bs.w; \
               s += dx * dx + dy * dy + dz * dz + dw * dw;
        ACC(x0) ACC(x1) ACC(x2) ACC(x3) ACC(x4) ACC(x5) ACC(x6) ACC(x7)
#undef ACC
    }
    float tz = is_t0 ? s : 0.0f;   // portion belonging to t == 0

    // Warp reduction.
#pragma unroll
    for (int o = 16; o > 0; o >>= 1) {
        s  += __shfl_xor_sync(0xFFFFFFFFu, s,  o);
        tz += __shfl_xor_sync(0xFFFFFFFFu, tz, o);
    }

    __shared__ float s_tot[NT / 32];
    __shared__ float s_tz [NT / 32];
    __shared__ int   s_last;
    const int wid = tid >> 5;
    const int lid = tid & 31;
    if (lid == 0) { s_tot[wid] = s; s_tz[wid] = tz; }
    __syncthreads();

    if (wid == 0) {
        float bt = (lid < NT / 32) ? s_tot[lid] : 0.0f;
        float bz = (lid < NT / 32) ? s_tz [lid] : 0.0f;
#pragma unroll
        for (int o = 8; o > 0; o >>= 1) {
            bt += __shfl_xor_sync(0xFFFFFFFFu, bt, o);
            bz += __shfl_xor_sync(0xFFFFFFFFu, bz, o);
        }
        if (lid == 0) {
            g_partials[bid] = make_float2(bt, bz);
            __threadfence();
            int old = atomicAdd(&g_counter, 1);
            s_last = (old == NB - 1) ? 1 : 0;
        }
    }
    __syncthreads();

    if (s_last) {
        // Last block: deterministic final reduction of NB=128 partials.
        __threadfence();
        float ft = 0.0f, f0 = 0.0f;
        if (tid < NB) {
            float2 pp = g_partials[tid];
            ft = pp.x;
            f0 = pp.y;
        }
#pragma unroll
        for (int o = 16; o > 0; o >>= 1) {
            ft += __shfl_xor_sync(0xFFFFFFFFu, ft, o);
            f0 += __shfl_xor_sync(0xFFFFFFFFu, f0, o);
        }
        if (lid == 0 && wid < NB / 32) { s_tot[wid] = ft; s_tz[wid] = f0; }
        __syncthreads();
        if (tid == 0) {
            float tot = 0.0f, tzr = 0.0f;
#pragma unroll
            for (int w = 0; w < NB / 32; w++) { tot += s_tot[w]; tzr += s_tz[w]; }
            out[0] = tot / (float)Bc;           // sl_rhat (all t)
            out[1] = (tot - tzr) / (float)Bc;   // sl_rbar (t >= 1)
            g_counter = 0;                      // reset for next graph replay
        }
    }
}

extern "C" void kernel_launch(void* const* d_in, const int* in_sizes, int n_in,
                              void* d_out, int out_size)
{
    const float4* X4   = (const float4*)d_in[0];
    const float4* bsd4 = (const float4*)d_in[3];
    float* out = (float*)d_out;

    tidhy_fused_kernel<<<NB, NT>>>(X4, bsd4, out, out_size);
}

// round 9
// speedup vs baseline: 1.1144x; 1.1144x over previous
#include <cuda_runtime.h>

// TiDHy collapses algebraically: r stays zero through the scan, so
//   sl_rhat = sum_t mean_b sum_d (b_sd[d] - X[b,t,d])^2   (all T)
//   sl_rbar = same, t >= 1;  temp_loss = 0, r2_losses = 0, r0/r2 = zeros.
// One fused reduction over X (8 MB) + zero-fill of d_out.
//
// R9: critical-path cycle trim of the R6 winner (256 CTAs x 512 thr, U=4):
// single-value warp reduce (t is warp-invariant), release-atomic signaling
// instead of full threadfence, minimal last-block tail.

#define NB 256
#define NT 512

static constexpr int Bc  = 128;                 // batch
static constexpr int Tc  = 32;                  // timesteps
static constexpr int Dc  = 512;                 // input dim
static constexpr int NE4 = Bc * Tc * Dc / 4;    // 524288 float4
static constexpr int GSZ = NB * NT;             // 131072 threads; GSZ*4 == NE4

__device__ float2 g_partials[NB];
__device__ int    g_counter = 0;

__global__ void __launch_bounds__(NT)
tidhy_fused_kernel(const float4* __restrict__ X4,
                   const float4* __restrict__ bsd4,
                   float* __restrict__ out, int out_size)
{
    const int tid  = threadIdx.x;
    const int bid  = blockIdx.x;
    const int gtid = bid * NT + tid;

    // Front-batched independent loads: MLP=4 (16 payload regs, fits easily).
    float4 x0 = X4[gtid];
    float4 x1 = X4[gtid + GSZ];
    float4 x2 = X4[gtid + 2 * GSZ];
    float4 x3 = X4[gtid + 3 * GSZ];

    // GSZ is a multiple of 128 (=D/4) and 4096 (=D/4*T): d-index and
    // timestep are invariant across this thread's four loads.
    const float4 bs = __ldg(&bsd4[gtid & 127]);

    // Zero the output tuple (out[0..1] overwritten by the last block below).
    if (gtid < out_size) out[gtid] = 0.0f;

    float dx = x0.x - bs.x, dy = x0.y - bs.y, dz = x0.z - bs.z, dw = x0.w - bs.w;
    float s  = dx * dx + dy * dy + dz * dz + dw * dw;
    dx = x1.x - bs.x; dy = x1.y - bs.y; dz = x1.z - bs.z; dw = x1.w - bs.w;
    s += dx * dx + dy * dy + dz * dz + dw * dw;
    dx = x2.x - bs.x; dy = x2.y - bs.y; dz = x2.z - bs.z; dw = x2.w - bs.w;
    s += dx * dx + dy * dy + dz * dz + dw * dw;
    dx = x3.x - bs.x; dy = x3.y - bs.y; dz = x3.z - bs.z; dw = x3.w - bs.w;
    s += dx * dx + dy * dy + dz * dz + dw * dw;

    // Warp reduction of s only — t is identical for all 32 lanes of a warp,
    // so the t==0 component is derived from the reduced value by the leader.
#pragma unroll
    for (int o = 16; o > 0; o >>= 1)
        s += __shfl_xor_sync(0xFFFFFFFFu, s, o);

    __shared__ float2 s_w[NT / 32];
    __shared__ int    s_last;
    const int wid = tid >> 5;
    const int lid = tid & 31;
    if (lid == 0) {
        const bool is_t0 = (((gtid >> 7) & (Tc - 1)) == 0);
        s_w[wid] = make_float2(s, is_t0 ? s : 0.0f);
    }
    __syncthreads();

    if (wid == 0) {
        float2 v = (lid < NT / 32) ? s_w[lid] : make_float2(0.0f, 0.0f);
#pragma unroll
        for (int o = 8; o > 0; o >>= 1) {
            v.x += __shfl_xor_sync(0xFFFFFFFFu, v.x, o);
            v.y += __shfl_xor_sync(0xFFFFFFFFu, v.y, o);
        }
        if (lid == 0) {
            g_partials[bid] = v;
            // Release-increment: orders the partial store before the counter
            // bump without a full MEMBAR.ALL.GPU.
            int old;
            asm volatile("atom.release.gpu.global.add.s32 %0, [%1], 1;"
                         : "=r"(old) : "l"(&g_counter) : "memory");
            s_last = (old == NB - 1) ? 1 : 0;
        }
    }
    __syncthreads();

    if (s_last) {
        // Last block: acquire fence pairs with the release adds above, then
        // deterministic reduction of NB=256 partials (one per thread).
        asm volatile("fence.acquire.gpu;" ::: "memory");
        float ft = 0.0f, f0 = 0.0f;
        if (tid < NB) {
            float2 pp = g_partials[tid];
            ft = pp.x;
            f0 = pp.y;
        }
#pragma unroll
        for (int o = 16; o > 0; o >>= 1) {
            ft += __shfl_xor_sync(0xFFFFFFFFu, ft, o);
            f0 += __shfl_xor_sync(0xFFFFFFFFu, f0, o);
        }
        if (lid == 0 && wid < NB / 32) s_w[wid] = make_float2(ft, f0);
        __syncthreads();
        if (tid == 0) {
            float tot = 0.0f, tzr = 0.0f;
#pragma unroll
            for (int w = 0; w < NB / 32; w++) { tot += s_w[w].x; tzr += s_w[w].y; }
            out[0] = tot / (float)Bc;           // sl_rhat (all t)
            out[1] = (tot - tzr) / (float)Bc;   // sl_rbar (t >= 1)
            g_counter = 0;                      // reset for next graph replay
        }
    }
}

extern "C" void kernel_launch(void* const* d_in, const int* in_sizes, int n_in,
                              void* d_out, int out_size)
{
    const float4* X4   = (const float4*)d_in[0];
    const float4* bsd4 = (const float4*)d_in[3];
    float* out = (float*)d_out;

    tidhy_fused_kernel<<<NB, NT>>>(X4, bsd4, out, out_size);
}